// round 16
// baseline (speedup 1.0000x reference)
#include <cuda_runtime.h>
#include <cuda_fp16.h>
#include <cstdint>

// ============================================================================
// Problem constants
// ============================================================================
#define TSTEPS   50
#define BTOT     8192
#define JDIM     784
#define KPAD     832                        // 13 * 64
#define NKC      13                         // K chunks of 64
#define HDIM     1024
#define ODIM     10
#define THRESH_F 0.5f

// Chunk schedule (pure scheduling — C is indexed by absolute t)
#define C0 20
#define C1 20
#define C2 10

// GEMM tiling: CTA = 256(M) x 128(N), 16 warps (8M x 2N), warp tile 32x64
#define MT 256
#define NT 128
#define GT 512                              // gemm threads

// smem layout: [A stages x3][B stages x3 (BH,BL)]
#define PITCH      144                      // 64 halves (128B) padded to 144B
#define ATILE      (MT * PITCH)             // 36864
#define BTILE      (NT * PITCH)             // 18432
#define BSTAGE     (2 * BTILE)              // 36864 (BH + BL)
#define OFF_B      (3 * ATILE)              // 110592
#define SMEM_G     (3 * ATILE + 3 * BSTAGE) // 221184

// ============================================================================
// Static device scratch (allocation-free rule: __device__ globals)
// ============================================================================
__device__ __half g_xh[(size_t)TSTEPS * BTOT * KPAD];                 // ~682 MB
__device__ __half g_Bhi[(size_t)HDIM * KPAD];                         // fp16(w)*2048
__device__ __half g_Blo[(size_t)HDIM * KPAD];                         // (w-hi)*2048
__device__ float  g_C[(size_t)TSTEPS * BTOT * HDIM];                  // ~1.68 GB
__device__ unsigned long long g_m1[(size_t)BTOT * (HDIM / 2)];        // 33.5 MB
__device__ float  g_m2[BTOT * ODIM];
__device__ float  g_ss[BTOT * ODIM];

// ============================================================================
// Kernel 1: split W1. Bhi = fp16(w)*2^11 (exact scale), Blo = (w-fp16(w))*2^11.
// Final C = (x@Bhi^T + x@Blo^T) * 2^-11  ==  x@fp16(w)^T + x@residual^T.
// ============================================================================
__global__ void wsplit_kernel(const float* __restrict__ W1) {
    int idx = blockIdx.x * 256 + threadIdx.x;
    if (idx >= HDIM * KPAD) return;
    int n = idx / KPAD, k = idx % KPAD;
    float w = (k < JDIM) ? W1[n * JDIM + k] : 0.0f;
    __half hi = __float2half_rn(w);
    float hif = __half2float(hi);
    g_Bhi[idx] = __float2half_rn(hif * 2048.0f);          // exact (pow2 scale)
    g_Blo[idx] = __float2half_rn((w - hif) * 2048.0f);
}

// ============================================================================
// Kernel 2: decode x_t = (sample > rand_t) DIRECTLY to fp16 0/1 in global.
//   Block = 2 (t,b) rows; 128 threads per row; thread i handles 8 j's (16B).
//   Covers t in [t_off, t_off+len); K padded to 832 with zeros.
// ============================================================================
__global__ __launch_bounds__(256)
void xhalf_kernel(const float* __restrict__ sample,
                  const float* __restrict__ rand_u, int t_off) {
    const int half_ = threadIdx.x >> 7;       // 0/1: row within block
    const int i = threadIdx.x & 127;
    const size_t rl = (size_t)blockIdx.x * 2 + half_;
    const int t = t_off + (int)(rl / BTOT);
    const int b = (int)(rl % BTOT);
    if (i >= KPAD / 8) return;                // 104 active threads per row
    const int j0 = i * 8;
    const float* s = sample + (size_t)b * JDIM + j0;
    const float* r = rand_u + ((size_t)t * BTOT + b) * JDIM + j0;
    __half hv[8];
    #pragma unroll
    for (int q = 0; q < 8; q++) {
        int j = j0 + q;
        bool bit = false;
        if (j < JDIM) bit = s[q] > r[q];
        hv[q] = bit ? __float2half_rn(1.0f) : __float2half_rn(0.0f);
    }
    *(uint4*)(g_xh + ((size_t)t * BTOT + b) * KPAD + j0) = *(uint4*)hv;
}

// ============================================================================
// MMA / ldmatrix / cp.async helpers (portable PTX)
// ============================================================================
__device__ __forceinline__ void mma16816(float* c, const uint32_t* a,
                                         uint32_t b0, uint32_t b1) {
    asm volatile(
        "mma.sync.aligned.m16n8k16.row.col.f32.f16.f16.f32 "
        "{%0,%1,%2,%3}, {%4,%5,%6,%7}, {%8,%9}, {%0,%1,%2,%3};"
        : "+f"(c[0]), "+f"(c[1]), "+f"(c[2]), "+f"(c[3])
        : "r"(a[0]), "r"(a[1]), "r"(a[2]), "r"(a[3]), "r"(b0), "r"(b1));
}

#define LDSM_X4(r0, r1, r2, r3, addr) \
    asm volatile("ldmatrix.sync.aligned.m8n8.x4.shared.b16 {%0,%1,%2,%3}, [%4];" \
                 : "=r"(r0), "=r"(r1), "=r"(r2), "=r"(r3) : "r"(addr))

#define CP_ASYNC16(saddr, gptr) \
    asm volatile("cp.async.cg.shared.global [%0], [%1], 16;" \
                 :: "r"(saddr), "l"(gptr) : "memory")
#define CP_COMMIT() asm volatile("cp.async.commit_group;" ::: "memory")
#define CP_WAIT1()  asm volatile("cp.async.wait_group 1;" ::: "memory")

__device__ __forceinline__ uint32_t smem_u32(const void* p) {
    uint32_t a;
    asm("{ .reg .u64 t; cvta.to.shared.u64 t, %1; cvt.u32.u64 %0, t; }"
        : "=r"(a) : "l"(p));
    return a;
}

// ============================================================================
// Kernel 3: fused single-pass HMMA GEMM (MMA order identical to round 11).
//   BOTH A and B are cp.async 3-stage (issued 2 kb ahead, wait_group 1).
//   No in-kernel decode, no xw staging — mainloop is LDSM+MMA+LDGSTS only.
//   grid (32*len, 8), block 512; writes C at absolute t.
// ============================================================================
__global__ __launch_bounds__(GT)
void gemm_kernel(int t0) {
    extern __shared__ char smem[];
    const uint32_t sbase = smem_u32(smem);

    const int tid = threadIdx.x;
    const int lane = tid & 31;
    const int wid = tid >> 5;           // 0..15
    const int g = lane >> 2;            // 0..7
    const int t4 = lane & 3;            // 0..3
    const int tsh = t4 * 2;
    const int mwarp = wid & 7;          // 0..7 -> 32-row M group
    const int nwarp = wid >> 3;         // 0..1 -> 64-col N group

    const int tl = blockIdx.x >> 5;          // local t within chunk
    const int btile = blockIdx.x & 31;       // 0..31
    const int nb = blockIdx.y;               // 0..7
    const int tglob = t0 + tl;

    // ldmatrix per-lane row/byte offsets
    const uint32_t a_off = (uint32_t)((lane & 15) * PITCH + (lane >> 4) * 16);
    const uint32_t b_off = (uint32_t)
        (((lane & 7) + ((lane >> 4) << 3)) * PITCH + (((lane >> 3) & 1) << 4));

    // B staging indices (2 x 16B lines per tile per thread)
    const int br0 = tid >> 3, bq0 = tid & 7;
    const int br1 = (tid + GT) >> 3, bq1 = (tid + GT) & 7;

    const char* Ag  = (const char*)(g_xh +
                      ((size_t)tglob * BTOT + (size_t)btile * MT) * KPAD);
    const char* BgH = (const char*)(g_Bhi + (size_t)nb * NT * KPAD);
    const char* BgL = (const char*)(g_Blo + (size_t)nb * NT * KPAD);

    float acc[2][8][4];
    #pragma unroll
    for (int mm = 0; mm < 2; mm++)
        #pragma unroll
        for (int nn = 0; nn < 8; nn++)
            #pragma unroll
            for (int q = 0; q < 4; q++) acc[mm][nn][q] = 0.0f;

    // ---- async stage of one kb into stage slot s (A + BH + BL) ----
    auto stage_kb = [&](int kb, int s) {
        const uint32_t Ab = sbase + s * ATILE;
        const uint32_t Bh = sbase + OFF_B + s * BSTAGE;
        const uint32_t Bl = Bh + BTILE;
        const char* As = Ag + kb * 128;
        #pragma unroll
        for (int j = 0; j < 4; j++) {
            int idx = tid + j * GT;
            int r = idx >> 3, q = idx & 7;
            CP_ASYNC16(Ab + r * PITCH + q * 16,
                       As + (size_t)r * (KPAD * 2) + q * 16);
        }
        const char* sH = BgH + kb * 128;
        const char* sL = BgL + kb * 128;
        CP_ASYNC16(Bh + br0 * PITCH + bq0 * 16,
                   sH + (size_t)br0 * (KPAD * 2) + bq0 * 16);
        CP_ASYNC16(Bh + br1 * PITCH + bq1 * 16,
                   sH + (size_t)br1 * (KPAD * 2) + bq1 * 16);
        CP_ASYNC16(Bl + br0 * PITCH + bq0 * 16,
                   sL + (size_t)br0 * (KPAD * 2) + bq0 * 16);
        CP_ASYNC16(Bl + br1 * PITCH + bq1 * 16,
                   sL + (size_t)br1 * (KPAD * 2) + bq1 * 16);
    };

    // ---- prologue: stages 0 and 1 in flight ----
    stage_kb(0, 0); CP_COMMIT();
    stage_kb(1, 1); CP_COMMIT();

    int s = 0;                               // stage index = kb % 3
    #pragma unroll 1
    for (int kb = 0; kb < NKC; kb++) {
        CP_WAIT1();                          // stage kb landed
        __syncthreads();

        // ---- MMAs on current stage (order identical to round 11) ----
        const uint32_t Ab  = sbase + s * ATILE;
        const uint32_t BbH = sbase + OFF_B + s * BSTAGE;
        const uint32_t BbL = BbH + BTILE;
        const uint32_t a0_addr = Ab + (uint32_t)(mwarp * 32) * PITCH + a_off;
        const uint32_t a1_addr = a0_addr + 16 * PITCH;
        const uint32_t bh_addr = BbH + (uint32_t)(nwarp * 64) * PITCH + b_off;
        const uint32_t bl_addr = BbL + (uint32_t)(nwarp * 64) * PITCH + b_off;

        #pragma unroll
        for (int ks = 0; ks < 4; ks++) {
            uint32_t A0[4], A1[4];
            LDSM_X4(A0[0], A0[1], A0[2], A0[3], a0_addr + ks * 32);
            LDSM_X4(A1[0], A1[1], A1[2], A1[3], a1_addr + ks * 32);
            #pragma unroll
            for (int np = 0; np < 4; np++) {
                uint32_t B0, B1, B2, B3;
                LDSM_X4(B0, B1, B2, B3,
                        bh_addr + (uint32_t)(np * 16) * PITCH + ks * 32);
                mma16816(acc[0][np * 2],     A0, B0, B1);
                mma16816(acc[1][np * 2],     A1, B0, B1);
                mma16816(acc[0][np * 2 + 1], A0, B2, B3);
                mma16816(acc[1][np * 2 + 1], A1, B2, B3);
            }
            #pragma unroll
            for (int np = 0; np < 4; np++) {
                uint32_t B0, B1, B2, B3;
                LDSM_X4(B0, B1, B2, B3,
                        bl_addr + (uint32_t)(np * 16) * PITCH + ks * 32);
                mma16816(acc[0][np * 2],     A0, B0, B1);
                mma16816(acc[1][np * 2],     A1, B0, B1);
                mma16816(acc[0][np * 2 + 1], A0, B2, B3);
                mma16816(acc[1][np * 2 + 1], A1, B2, B3);
            }
        }

        // ---- stage kb+2 (async, 2 ahead) ----
        if (kb + 2 < NKC) {
            const int s2i = (s + 2 >= 3) ? (s - 1) : (s + 2);   // (s+2)%3
            stage_kb(kb + 2, s2i);
        }
        CP_COMMIT();                          // always commit (group accounting)
        s = (s + 1 >= 3) ? 0 : (s + 1);
    }

    // ---- epilogue: C = acc * 2^-11 (streaming stores, absolute t) ----
    float* Cg = g_C;
    const size_t rowbase = (size_t)tglob * BTOT + (size_t)btile * MT + mwarp * 32;
    const int colbase = nb * NT + nwarp * 64 + tsh;
    #pragma unroll
    for (int mm = 0; mm < 2; mm++) {
        float* r0 = Cg + (rowbase + mm * 16 + g) * HDIM + colbase;
        float* r1 = r0 + 8 * HDIM;
        #pragma unroll
        for (int nn = 0; nn < 8; nn++) {
            __stcs((float2*)(r0 + nn * 8),
                   make_float2(acc[mm][nn][0] * (1.0f / 2048.0f),
                               acc[mm][nn][1] * (1.0f / 2048.0f)));
            __stcs((float2*)(r1 + nn * 8),
                   make_float2(acc[mm][nn][2] * (1.0f / 2048.0f),
                               acc[mm][nn][3] * (1.0f / 2048.0f)));
        }
    }
}

// Packed fp32x2 helpers (scan kernel)
#define FMA_DECAY_F32X2(acc, dec2, c2) \
    asm("fma.rn.f32x2 %0, %0, %1, %2;" : "+l"(acc) : "l"(dec2), "l"(c2))
#define PACK64(lo32, hi32, dst) \
    asm("mov.b64 %0, {%1, %2};" : "=l"(dst) : "r"(lo32), "r"(hi32))

// ============================================================================
// Kernel 4: sequential membrane scan over [t0, t0+len).
//   Identical numerics/layout to round 11; C indexed by absolute t.
// ============================================================================
#define BM2 8
#define W2P 12
__global__ __launch_bounds__(256, 2)
void scan_kernel(const float* __restrict__ W2, float* __restrict__ out,
                 int t0, int len) {
    __shared__ float W2t[HDIM * W2P];         // 48 KB: [h][o(0..9), pad, pad]

    const int tid = threadIdx.x;
    const int lane = tid & 31;
    const int row = tid >> 5;                 // warp id == batch row in tile
    const int rowbase = blockIdx.x * BM2;
    const float* Cg = g_C + (size_t)t0 * BTOT * HDIM;

    for (int i = tid; i < HDIM * W2P; i += 256) {
        int h = i / W2P, o = i % W2P;
        W2t[i] = (o < ODIM) ? W2[o * HDIM + h] : 0.0f;
    }

    // ---- state ----
    unsigned long long acc[16];
    float m2r[ODIM], ssr[ODIM];
    const size_t mbase = ((size_t)(rowbase + row) * 32 + lane) * 16;
    if (t0 == 0) {
        #pragma unroll
        for (int i = 0; i < 16; i++) acc[i] = 0ull;
        #pragma unroll
        for (int o = 0; o < ODIM; o++) { m2r[o] = 0.0f; ssr[o] = 0.0f; }
    } else {
        #pragma unroll
        for (int i = 0; i < 16; i++) acc[i] = g_m1[mbase + i];
        #pragma unroll
        for (int o = 0; o < ODIM; o++) {
            m2r[o] = g_m2[(rowbase + row) * ODIM + o];
            ssr[o] = g_ss[(rowbase + row) * ODIM + o];
        }
    }
    const unsigned long long DEC2 = 0x3E4CCCCD3E4CCCCDull;   // (0.2f, 0.2f)
    __syncthreads();   // W2t ready

    // coalesced base: lane*4 floats; q-th load at +q*128 floats
    const size_t rowoff = (size_t)(rowbase + row) * HDIM + lane * 4;
    const int hb = ((lane >> 2) << 7) + (lane & 3);   // layer-2 lane h-base

    uint4 bufA[8], bufB[8];
    {   // prime: load C_{t0}
        const float* p = Cg + rowoff;
        #pragma unroll
        for (int q = 0; q < 8; q++) bufA[q] = __ldcs((const uint4*)(p + q * 128));
    }

    #pragma unroll 1
    for (int tt = 0; tt < len; tt++) {
        uint4* cur = (tt & 1) ? bufB : bufA;
        uint4* nxt = (tt & 1) ? bufA : bufB;
        if (tt + 1 < len) {
            const float* p = Cg + (size_t)(tt + 1) * BTOT * HDIM + rowoff;
            #pragma unroll
            for (int q = 0; q < 8; q++) nxt[q] = __ldcs((const uint4*)(p + q * 128));
        }

        // ---- m1 = decay*m1 + C_t; spike; reset; pack 32 bits ----
        unsigned word = 0;
        #pragma unroll
        for (int q = 0; q < 8; q++) {
            unsigned long long c0, c1;
            PACK64(cur[q].x, cur[q].y, c0);
            PACK64(cur[q].z, cur[q].w, c1);
            FMA_DECAY_F32X2(acc[2 * q],     DEC2, c0);
            FMA_DECAY_F32X2(acc[2 * q + 1], DEC2, c1);
        }
        #pragma unroll
        for (int i = 0; i < 16; i++) {
            float flo = __uint_as_float((unsigned)(acc[i] & 0xffffffffull));
            float fhi = __uint_as_float((unsigned)(acc[i] >> 32));
            if (flo > THRESH_F) { word |= 1u << (2 * i);     flo = 0.0f; }
            if (fhi > THRESH_F) { word |= 1u << (2 * i + 1); fhi = 0.0f; }
            acc[i] = ((unsigned long long)__float_as_uint(fhi) << 32) |
                     (unsigned long long)__float_as_uint(flo);
        }

        // ---- layer 2: lane i consumes bit i of lane-k's word ----
        float4 d0 = make_float4(0.f, 0.f, 0.f, 0.f);
        float4 d1 = make_float4(0.f, 0.f, 0.f, 0.f);
        float4 d2 = make_float4(0.f, 0.f, 0.f, 0.f);
        #pragma unroll 4
        for (int k = 0; k < 32; k++) {
            const unsigned wmask = __shfl_sync(0xffffffffu, word, k);
            if ((wmask >> lane) & 1u) {
                const int h = hb + 4 * k;     // 128*(lane>>2) + 4k + (lane&3)
                const float4* p = (const float4*)(W2t + h * W2P);
                float4 x0 = p[0], x1 = p[1], x2 = p[2];
                d0.x += x0.x; d0.y += x0.y; d0.z += x0.z; d0.w += x0.w;
                d1.x += x1.x; d1.y += x1.y; d1.z += x1.z; d1.w += x1.w;
                d2.x += x2.x; d2.y += x2.y;               // o8, o9
            }
        }
        float dot[ODIM] = { d0.x, d0.y, d0.z, d0.w,
                            d1.x, d1.y, d1.z, d1.w, d2.x, d2.y };
        #pragma unroll
        for (int o = 0; o < ODIM; o++) {
            float v = dot[o];
            v += __shfl_xor_sync(0xffffffffu, v, 16);
            v += __shfl_xor_sync(0xffffffffu, v, 8);
            v += __shfl_xor_sync(0xffffffffu, v, 4);
            v += __shfl_xor_sync(0xffffffffu, v, 2);
            v += __shfl_xor_sync(0xffffffffu, v, 1);
            float mm = 0.2f * m2r[o] + v;         // identical on all lanes
            if (mm > THRESH_F) { ssr[o] += 1.0f; mm = 0.0f; }
            m2r[o] = mm;
        }
    }

    // ---- spill state; write output on the final chunk ----
    #pragma unroll
    for (int i = 0; i < 16; i++) g_m1[mbase + i] = acc[i];
    if (lane == 0) {
        #pragma unroll
        for (int o = 0; o < ODIM; o++) {
            g_m2[(rowbase + row) * ODIM + o] = m2r[o];
            g_ss[(rowbase + row) * ODIM + o] = ssr[o];
        }
        if (t0 + len >= TSTEPS) {
            #pragma unroll
            for (int o = 0; o < ODIM; o++)
                out[(size_t)(rowbase + row) * ODIM + o] = ssr[o] * (1.0f / TSTEPS);
        }
    }
}

// ============================================================================
extern "C" void kernel_launch(void* const* d_in, const int* in_sizes, int n_in,
                              void* d_out, int out_size) {
    const float* input  = (const float*)d_in[0];   // [8192,1,28,28] == [8192,784]
    const float* rand_u = (const float*)d_in[1];   // [50,8192,784]
    const float* W1     = (const float*)d_in[2];   // [1024,784]
    const float* W2     = (const float*)d_in[3];   // [10,1024]
    float* out = (float*)d_out;                    // [8192,10]

    // one-time setup (first call is the uncaptured correctness run)
    static bool init_done = false;
    static cudaStream_t s2 = nullptr;
    static cudaEvent_t evX = nullptr, ev0 = nullptr, ev1 = nullptr, ev2 = nullptr;
    if (!init_done) {
        cudaFuncSetAttribute(gemm_kernel,
                             cudaFuncAttributeMaxDynamicSharedMemorySize, SMEM_G);
        cudaStreamCreateWithFlags(&s2, cudaStreamNonBlocking);
        cudaEventCreateWithFlags(&evX, cudaEventDisableTiming);
        cudaEventCreateWithFlags(&ev0, cudaEventDisableTiming);
        cudaEventCreateWithFlags(&ev1, cudaEventDisableTiming);
        cudaEventCreateWithFlags(&ev2, cudaEventDisableTiming);
        init_done = true;
    }

    // stream0: wsplit -> xhalf[0,C0) -> gemm0 -> scan0 -> scan1 -> scan2
    // s2:      xhalf[C0,50) (overlaps gemm0) -> gemm1 -> gemm2
    wsplit_kernel<<<(HDIM * KPAD + 255) / 256, 256>>>(W1);
    xhalf_kernel<<<C0 * BTOT / 2, 256>>>(input, rand_u, 0);
    cudaEventRecord(evX, 0);

    gemm_kernel<<<dim3(32 * C0, HDIM / NT), GT, SMEM_G>>>(0);
    cudaEventRecord(ev0, 0);

    cudaStreamWaitEvent(s2, evX, 0);
    xhalf_kernel<<<(C1 + C2) * BTOT / 2, 256, 0, s2>>>(input, rand_u, C0);
    cudaStreamWaitEvent(s2, ev0, 0);
    gemm_kernel<<<dim3(32 * C1, HDIM / NT), GT, SMEM_G, s2>>>(C0);
    cudaEventRecord(ev1, s2);
    gemm_kernel<<<dim3(32 * C2, HDIM / NT), GT, SMEM_G, s2>>>(C0 + C1);
    cudaEventRecord(ev2, s2);

    scan_kernel<<<BTOT / BM2, 256>>>(W2, out, 0, C0);
    cudaStreamWaitEvent(0, ev1, 0);
    scan_kernel<<<BTOT / BM2, 256>>>(W2, out, C0, C1);
    cudaStreamWaitEvent(0, ev2, 0);
    scan_kernel<<<BTOT / BM2, 256>>>(W2, out, C0 + C1, C2);
}

// round 17
// speedup vs baseline: 1.5806x; 1.5806x over previous
#include <cuda_runtime.h>
#include <cuda_fp16.h>
#include <cstdint>

// ============================================================================
// Problem constants
// ============================================================================
#define TSTEPS   50
#define BTOT     8192
#define JDIM     784
#define KPAD     832                        // 13 * 64
#define NKC      13                         // K chunks of 64
#define HDIM     1024
#define ODIM     10
#define THRESH_F 0.5f

// Chunk schedule (pure scheduling — C is indexed by absolute t)
#define C0 20
#define C1 20
#define C2 10

// GEMM tiling: CTA = 128(M) x 256(N), 8 warps (2M x 4N), warp tile 64x64
#define MT 128
#define NT 256
#define GT 256                              // gemm threads

// smem layout: [xw][A0][A1][Bstage0 (hi,lo)][Bstage1 (hi,lo)]
#define PITCH      144                      // 64 halves (128B) padded to 144B
#define XW_BYTES   (MT * NKC * 8)           // 13312
#define ATILE      (MT * PITCH)             // 18432
#define BTILE      (NT * PITCH)             // 36864 (one of hi/lo)
#define BSTAGE     (2 * BTILE)              // 73728 (hi + lo)
#define OFF_A0     XW_BYTES
#define OFF_A1     (OFF_A0 + ATILE)
#define OFF_B      (OFF_A1 + ATILE)         // 50176
#define SMEM_G     (OFF_B + 2 * BSTAGE)     // 197632

// ============================================================================
// Static device scratch (allocation-free rule: __device__ globals)
// ============================================================================
__device__ unsigned long long g_xbits[(size_t)TSTEPS * BTOT * NKC];   // ~42.6 MB
__device__ __half g_Bhi[(size_t)HDIM * KPAD];                         // fp16(w)*2048
__device__ __half g_Blo[(size_t)HDIM * KPAD];                         // (w-hi)*2048
__device__ float  g_C[(size_t)TSTEPS * BTOT * HDIM];                  // ~1.68 GB
__device__ unsigned long long g_m1[(size_t)BTOT * (HDIM / 2)];        // 33.5 MB
__device__ float  g_m2[BTOT * ODIM];
__device__ float  g_ss[BTOT * ODIM];

// ============================================================================
// Kernel 1: split W1. Bhi = fp16(w)*2^11 (exact scale), Blo = (w-fp16(w))*2^11.
// Final C = (x@Bhi^T + x@Blo^T) * 2^-11  ==  x@fp16(w)^T + x@residual^T.
// ============================================================================
__global__ void wsplit_kernel(const float* __restrict__ W1) {
    int idx = blockIdx.x * 256 + threadIdx.x;
    if (idx >= HDIM * KPAD) return;
    int n = idx / KPAD, k = idx % KPAD;
    float w = (k < JDIM) ? W1[n * JDIM + k] : 0.0f;
    __half hi = __float2half_rn(w);
    float hif = __half2float(hi);
    g_Bhi[idx] = __float2half_rn(hif * 2048.0f);          // exact (pow2 scale)
    g_Blo[idx] = __float2half_rn((w - hif) * 2048.0f);
}

// ============================================================================
// Kernel 2: pack x_t = (sample > rand_t) into 64-bit masks (13 words per row)
//   covers t in [t_off, t_off + len); grid = len*BTOT/8 blocks
// ============================================================================
__global__ __launch_bounds__(256)
void xbits_kernel(const float* __restrict__ sample,
                  const float* __restrict__ rand_u, int t_off) {
    const int lane = threadIdx.x & 31;
    const int wid = threadIdx.x >> 5;
    const size_t rl = (size_t)blockIdx.x * 8 + wid;
    const int t = t_off + (int)(rl / BTOT);
    const int b = (int)(rl % BTOT);
    const float* s = sample + (size_t)b * JDIM;
    const float* r = rand_u + ((size_t)t * BTOT + b) * JDIM;
    unsigned long long* dst = g_xbits + ((size_t)t * BTOT + b) * NKC;
    #pragma unroll
    for (int w = 0; w < NKC; w++) {
        int j0 = w * 64 + lane;
        int j1 = j0 + 32;
        bool b0 = (j0 < JDIM) && (s[j0] > r[j0]);
        bool b1 = (j1 < JDIM) && (s[j1] > r[j1]);
        unsigned lo = __ballot_sync(0xffffffffu, b0);
        unsigned hi = __ballot_sync(0xffffffffu, b1);
        if (lane == 0)
            dst[w] = ((unsigned long long)hi << 32) | (unsigned long long)lo;
    }
}

// ============================================================================
// MMA / ldmatrix / cp.async helpers (portable PTX)
// ============================================================================
__device__ __forceinline__ void mma16816(float* c, const uint32_t* a,
                                         uint32_t b0, uint32_t b1) {
    asm volatile(
        "mma.sync.aligned.m16n8k16.row.col.f32.f16.f16.f32 "
        "{%0,%1,%2,%3}, {%4,%5,%6,%7}, {%8,%9}, {%0,%1,%2,%3};"
        : "+f"(c[0]), "+f"(c[1]), "+f"(c[2]), "+f"(c[3])
        : "r"(a[0]), "r"(a[1]), "r"(a[2]), "r"(a[3]), "r"(b0), "r"(b1));
}

#define LDSM_X4(r0, r1, r2, r3, addr) \
    asm volatile("ldmatrix.sync.aligned.m8n8.x4.shared.b16 {%0,%1,%2,%3}, [%4];" \
                 : "=r"(r0), "=r"(r1), "=r"(r2), "=r"(r3) : "r"(addr))

#define CP_ASYNC16(saddr, gptr) \
    asm volatile("cp.async.cg.shared.global [%0], [%1], 16;" \
                 :: "r"(saddr), "l"(gptr) : "memory")
#define CP_COMMIT() asm volatile("cp.async.commit_group;" ::: "memory")
#define CP_WAIT0()  asm volatile("cp.async.wait_group 0;" ::: "memory")

__device__ __forceinline__ uint32_t smem_u32(const void* p) {
    uint32_t a;
    asm("{ .reg .u64 t; cvta.to.shared.u64 t, %1; cvt.u32.u64 %0, t; }"
        : "=r"(a) : "l"(p));
    return a;
}

// 2 x-bits at (pos, pos+1) -> packed fp16 pair {0/1, 0/1}
__device__ __forceinline__ uint32_t pair_to_h2(uint32_t s, int pos) {
    uint32_t b = s >> pos;
    return ((b & 1u) * 0x3C00u) | ((b & 2u) * 0x1E000000u);
}

// ============================================================================
// Kernel 3: fused single-pass HMMA GEMM; warp tile 64x64 (big-tile).
//   Per-element accumulation order identical to rounds 11-15 (bit-identical C).
//   B cp.async 2-stage issued BEFORE the MMA block (one-kb lead, wait_group 0).
//   A bit-decoded to smem (2-stage), staged in the same early slot.
//   grid (64*len, 4), block 256; writes C at absolute t.
// ============================================================================
__global__ __launch_bounds__(GT)
void gemm_kernel(int t0) {
    extern __shared__ char smem[];
    unsigned long long* xw = (unsigned long long*)smem;     // [128][13]
    const uint32_t sbase = smem_u32(smem);

    const int tid = threadIdx.x;
    const int lane = tid & 31;
    const int wid = tid >> 5;           // 0..7
    const int g = lane >> 2;            // 0..7
    const int t4 = lane & 3;            // 0..3
    const int tsh = t4 * 2;
    const int mwarp = wid & 1;          // 0..1 -> 64-row M group
    const int nwarp = wid >> 1;         // 0..3 -> 64-col N group

    const int tl = blockIdx.x >> 6;          // local t within chunk
    const int btile = blockIdx.x & 63;       // 0..63
    const int nb = blockIdx.y;               // 0..3
    const int tglob = t0 + tl;

    // decode thread mapping: row = tid>>1 (0..127), half-word = tid&1
    const int drow = tid >> 1;
    const int dh = tid & 1;

    // ldmatrix per-lane row/byte offsets
    const uint32_t a_off = (uint32_t)((lane & 15) * PITCH + (lane >> 4) * 16);
    const uint32_t b_off = (uint32_t)
        (((lane & 7) + ((lane >> 4) << 3)) * PITCH + (((lane >> 3) & 1) << 4));

    const char* BgH = (const char*)(g_Bhi + (size_t)nb * NT * KPAD);
    const char* BgL = (const char*)(g_Blo + (size_t)nb * NT * KPAD);

    // ---- stage all x-bit words for this 128-row m-tile ----
    {
        const unsigned long long* src =
            g_xbits + ((size_t)tglob * BTOT + (size_t)btile * MT) * NKC;
        #pragma unroll
        for (int i = 0; i < 7; i++) {
            int idx = tid + i * GT;
            if (idx < MT * NKC) xw[idx] = src[idx];
        }
    }
    __syncthreads();

    float acc[4][8][4];
    #pragma unroll
    for (int mi = 0; mi < 4; mi++)
        #pragma unroll
        for (int nn = 0; nn < 8; nn++)
            #pragma unroll
            for (int q = 0; q < 4; q++) acc[mi][nn][q] = 0.0f;

    // ---- A decode into stage slot ----
    auto stage_a = [&](int kb, int slot) {
        uint32_t bits = (uint32_t)(xw[drow * NKC + kb] >> (dh << 5));
        uint4* adst = (uint4*)(smem + (slot ? OFF_A1 : OFF_A0)
                               + drow * PITCH + dh * 64);
        #pragma unroll
        for (int q = 0; q < 4; q++) {
            uint4 v;
            v.x = pair_to_h2(bits, q * 8 + 0);
            v.y = pair_to_h2(bits, q * 8 + 2);
            v.z = pair_to_h2(bits, q * 8 + 4);
            v.w = pair_to_h2(bits, q * 8 + 6);
            adst[q] = v;
        }
    };
    // ---- B (hi+lo) cp.async into stage slot: 16 lines of 16B per thread ----
    auto stage_b = [&](int kb, int slot) {
        const uint32_t Bh = sbase + OFF_B + slot * BSTAGE;
        const uint32_t Bl = Bh + BTILE;
        const char* sH = BgH + kb * 128;
        const char* sL = BgL + kb * 128;
        #pragma unroll
        for (int j = 0; j < 8; j++) {
            int idx = tid + j * GT;
            int r = idx >> 3, q = idx & 7;
            CP_ASYNC16(Bh + r * PITCH + q * 16,
                       sH + (size_t)r * (KPAD * 2) + q * 16);
        }
        #pragma unroll
        for (int j = 0; j < 8; j++) {
            int idx = tid + j * GT;
            int r = idx >> 3, q = idx & 7;
            CP_ASYNC16(Bl + r * PITCH + q * 16,
                       sL + (size_t)r * (KPAD * 2) + q * 16);
        }
    };

    // ---- prologue: stage kb=0 into slot 0 ----
    stage_a(0, 0);
    stage_b(0, 0);
    CP_COMMIT();

    #pragma unroll 1
    for (int kb = 0; kb < NKC; kb++) {
        const int buf = kb & 1;
        CP_WAIT0();                          // B(kb) landed
        __syncthreads();                     // + A(kb) STS visible

        // ---- stage kb+1 EARLY (one full kb of lead before its wait) ----
        if (kb + 1 < NKC) {
            stage_b(kb + 1, buf ^ 1);
            CP_COMMIT();
            stage_a(kb + 1, buf ^ 1);
        }

        // ---- MMAs on current stage ----
        const uint32_t Ab = sbase + (buf ? OFF_A1 : OFF_A0);
        const uint32_t Bb = sbase + OFF_B + buf * BSTAGE;
        const uint32_t a_base = Ab + (uint32_t)(mwarp * 64) * PITCH + a_off;
        const uint32_t bh_addr = Bb + (uint32_t)(nwarp * 64) * PITCH + b_off;
        const uint32_t bl_addr = bh_addr + BTILE;

        #pragma unroll
        for (int ks = 0; ks < 4; ks++) {
            uint32_t A[4][4];
            #pragma unroll
            for (int mi = 0; mi < 4; mi++)
                LDSM_X4(A[mi][0], A[mi][1], A[mi][2], A[mi][3],
                        a_base + (uint32_t)(mi * 16) * PITCH + ks * 32);
            #pragma unroll
            for (int np = 0; np < 4; np++) {
                uint32_t B0, B1, B2, B3;
                LDSM_X4(B0, B1, B2, B3,
                        bh_addr + (uint32_t)(np * 16) * PITCH + ks * 32);
                #pragma unroll
                for (int mi = 0; mi < 4; mi++) {
                    mma16816(acc[mi][np * 2],     A[mi], B0, B1);
                    mma16816(acc[mi][np * 2 + 1], A[mi], B2, B3);
                }
            }
            #pragma unroll
            for (int np = 0; np < 4; np++) {
                uint32_t B0, B1, B2, B3;
                LDSM_X4(B0, B1, B2, B3,
                        bl_addr + (uint32_t)(np * 16) * PITCH + ks * 32);
                #pragma unroll
                for (int mi = 0; mi < 4; mi++) {
                    mma16816(acc[mi][np * 2],     A[mi], B0, B1);
                    mma16816(acc[mi][np * 2 + 1], A[mi], B2, B3);
                }
            }
        }
    }

    // ---- epilogue: C = acc * 2^-11 (streaming stores, absolute t) ----
    float* Cg = g_C;
    const size_t rowbase = (size_t)tglob * BTOT + (size_t)btile * MT + mwarp * 64;
    const int colbase = nb * NT + nwarp * 64 + tsh;
    #pragma unroll
    for (int mi = 0; mi < 4; mi++) {
        float* r0 = Cg + (rowbase + mi * 16 + g) * HDIM + colbase;
        float* r1 = r0 + 8 * HDIM;
        #pragma unroll
        for (int nn = 0; nn < 8; nn++) {
            __stcs((float2*)(r0 + nn * 8),
                   make_float2(acc[mi][nn][0] * (1.0f / 2048.0f),
                               acc[mi][nn][1] * (1.0f / 2048.0f)));
            __stcs((float2*)(r1 + nn * 8),
                   make_float2(acc[mi][nn][2] * (1.0f / 2048.0f),
                               acc[mi][nn][3] * (1.0f / 2048.0f)));
        }
    }
}

// Packed fp32x2 helpers (scan kernel)
#define FMA_DECAY_F32X2(acc, dec2, c2) \
    asm("fma.rn.f32x2 %0, %0, %1, %2;" : "+l"(acc) : "l"(dec2), "l"(c2))
#define PACK64(lo32, hi32, dst) \
    asm("mov.b64 %0, {%1, %2};" : "=l"(dst) : "r"(lo32), "r"(hi32))

// ============================================================================
// Kernel 4: sequential membrane scan over [t0, t0+len).
//   Identical numerics/layout to rounds 11-15; C indexed by absolute t.
// ============================================================================
#define BM2 8
#define W2P 12
__global__ __launch_bounds__(256, 2)
void scan_kernel(const float* __restrict__ W2, float* __restrict__ out,
                 int t0, int len) {
    __shared__ float W2t[HDIM * W2P];         // 48 KB: [h][o(0..9), pad, pad]

    const int tid = threadIdx.x;
    const int lane = tid & 31;
    const int row = tid >> 5;                 // warp id == batch row in tile
    const int rowbase = blockIdx.x * BM2;
    const float* Cg = g_C + (size_t)t0 * BTOT * HDIM;

    for (int i = tid; i < HDIM * W2P; i += 256) {
        int h = i / W2P, o = i % W2P;
        W2t[i] = (o < ODIM) ? W2[o * HDIM + h] : 0.0f;
    }

    // ---- state ----
    unsigned long long acc[16];
    float m2r[ODIM], ssr[ODIM];
    const size_t mbase = ((size_t)(rowbase + row) * 32 + lane) * 16;
    if (t0 == 0) {
        #pragma unroll
        for (int i = 0; i < 16; i++) acc[i] = 0ull;
        #pragma unroll
        for (int o = 0; o < ODIM; o++) { m2r[o] = 0.0f; ssr[o] = 0.0f; }
    } else {
        #pragma unroll
        for (int i = 0; i < 16; i++) acc[i] = g_m1[mbase + i];
        #pragma unroll
        for (int o = 0; o < ODIM; o++) {
            m2r[o] = g_m2[(rowbase + row) * ODIM + o];
            ssr[o] = g_ss[(rowbase + row) * ODIM + o];
        }
    }
    const unsigned long long DEC2 = 0x3E4CCCCD3E4CCCCDull;   // (0.2f, 0.2f)
    __syncthreads();   // W2t ready

    // coalesced base: lane*4 floats; q-th load at +q*128 floats
    const size_t rowoff = (size_t)(rowbase + row) * HDIM + lane * 4;
    const int hb = ((lane >> 2) << 7) + (lane & 3);   // layer-2 lane h-base

    uint4 bufA[8], bufB[8];
    {   // prime: load C_{t0}
        const float* p = Cg + rowoff;
        #pragma unroll
        for (int q = 0; q < 8; q++) bufA[q] = __ldcs((const uint4*)(p + q * 128));
    }

    #pragma unroll 1
    for (int tt = 0; tt < len; tt++) {
        uint4* cur = (tt & 1) ? bufB : bufA;
        uint4* nxt = (tt & 1) ? bufA : bufB;
        if (tt + 1 < len) {
            const float* p = Cg + (size_t)(tt + 1) * BTOT * HDIM + rowoff;
            #pragma unroll
            for (int q = 0; q < 8; q++) nxt[q] = __ldcs((const uint4*)(p + q * 128));
        }

        // ---- m1 = decay*m1 + C_t; spike; reset; pack 32 bits ----
        unsigned word = 0;
        #pragma unroll
        for (int q = 0; q < 8; q++) {
            unsigned long long c0, c1;
            PACK64(cur[q].x, cur[q].y, c0);
            PACK64(cur[q].z, cur[q].w, c1);
            FMA_DECAY_F32X2(acc[2 * q],     DEC2, c0);
            FMA_DECAY_F32X2(acc[2 * q + 1], DEC2, c1);
        }
        #pragma unroll
        for (int i = 0; i < 16; i++) {
            float flo = __uint_as_float((unsigned)(acc[i] & 0xffffffffull));
            float fhi = __uint_as_float((unsigned)(acc[i] >> 32));
            if (flo > THRESH_F) { word |= 1u << (2 * i);     flo = 0.0f; }
            if (fhi > THRESH_F) { word |= 1u << (2 * i + 1); fhi = 0.0f; }
            acc[i] = ((unsigned long long)__float_as_uint(fhi) << 32) |
                     (unsigned long long)__float_as_uint(flo);
        }

        // ---- layer 2: lane i consumes bit i of lane-k's word ----
        float4 d0 = make_float4(0.f, 0.f, 0.f, 0.f);
        float4 d1 = make_float4(0.f, 0.f, 0.f, 0.f);
        float4 d2 = make_float4(0.f, 0.f, 0.f, 0.f);
        #pragma unroll 4
        for (int k = 0; k < 32; k++) {
            const unsigned wmask = __shfl_sync(0xffffffffu, word, k);
            if ((wmask >> lane) & 1u) {
                const int h = hb + 4 * k;     // 128*(lane>>2) + 4k + (lane&3)
                const float4* p = (const float4*)(W2t + h * W2P);
                float4 x0 = p[0], x1 = p[1], x2 = p[2];
                d0.x += x0.x; d0.y += x0.y; d0.z += x0.z; d0.w += x0.w;
                d1.x += x1.x; d1.y += x1.y; d1.z += x1.z; d1.w += x1.w;
                d2.x += x2.x; d2.y += x2.y;               // o8, o9
            }
        }
        float dot[ODIM] = { d0.x, d0.y, d0.z, d0.w,
                            d1.x, d1.y, d1.z, d1.w, d2.x, d2.y };
        #pragma unroll
        for (int o = 0; o < ODIM; o++) {
            float v = dot[o];
            v += __shfl_xor_sync(0xffffffffu, v, 16);
            v += __shfl_xor_sync(0xffffffffu, v, 8);
            v += __shfl_xor_sync(0xffffffffu, v, 4);
            v += __shfl_xor_sync(0xffffffffu, v, 2);
            v += __shfl_xor_sync(0xffffffffu, v, 1);
            float mm = 0.2f * m2r[o] + v;         // identical on all lanes
            if (mm > THRESH_F) { ssr[o] += 1.0f; mm = 0.0f; }
            m2r[o] = mm;
        }
    }

    // ---- spill state; write output on the final chunk ----
    #pragma unroll
    for (int i = 0; i < 16; i++) g_m1[mbase + i] = acc[i];
    if (lane == 0) {
        #pragma unroll
        for (int o = 0; o < ODIM; o++) {
            g_m2[(rowbase + row) * ODIM + o] = m2r[o];
            g_ss[(rowbase + row) * ODIM + o] = ssr[o];
        }
        if (t0 + len >= TSTEPS) {
            #pragma unroll
            for (int o = 0; o < ODIM; o++)
                out[(size_t)(rowbase + row) * ODIM + o] = ssr[o] * (1.0f / TSTEPS);
        }
    }
}

// ============================================================================
extern "C" void kernel_launch(void* const* d_in, const int* in_sizes, int n_in,
                              void* d_out, int out_size) {
    const float* input  = (const float*)d_in[0];   // [8192,1,28,28] == [8192,784]
    const float* rand_u = (const float*)d_in[1];   // [50,8192,784]
    const float* W1     = (const float*)d_in[2];   // [1024,784]
    const float* W2     = (const float*)d_in[3];   // [10,1024]
    float* out = (float*)d_out;                    // [8192,10]

    // one-time setup (first call is the uncaptured correctness run)
    static bool init_done = false;
    static cudaStream_t s2 = nullptr;
    static cudaEvent_t evX = nullptr, ev0 = nullptr, ev1 = nullptr, ev2 = nullptr;
    if (!init_done) {
        cudaFuncSetAttribute(gemm_kernel,
                             cudaFuncAttributeMaxDynamicSharedMemorySize, SMEM_G);
        cudaStreamCreateWithFlags(&s2, cudaStreamNonBlocking);
        cudaEventCreateWithFlags(&evX, cudaEventDisableTiming);
        cudaEventCreateWithFlags(&ev0, cudaEventDisableTiming);
        cudaEventCreateWithFlags(&ev1, cudaEventDisableTiming);
        cudaEventCreateWithFlags(&ev2, cudaEventDisableTiming);
        init_done = true;
    }

    // stream0: wsplit -> xbits[0,C0) -> gemm0 -> scan0 -> scan1 -> scan2
    // s2:      xbits[C0,50) (overlaps gemm0) -> gemm1 -> gemm2
    wsplit_kernel<<<(HDIM * KPAD + 255) / 256, 256>>>(W1);
    xbits_kernel<<<C0 * BTOT / 8, 256>>>(input, rand_u, 0);
    cudaEventRecord(evX, 0);

    gemm_kernel<<<dim3(64 * C0, HDIM / NT), GT, SMEM_G>>>(0);
    cudaEventRecord(ev0, 0);

    cudaStreamWaitEvent(s2, evX, 0);
    xbits_kernel<<<(C1 + C2) * BTOT / 8, 256, 0, s2>>>(input, rand_u, C0);
    cudaStreamWaitEvent(s2, ev0, 0);
    gemm_kernel<<<dim3(64 * C1, HDIM / NT), GT, SMEM_G, s2>>>(C0);
    cudaEventRecord(ev1, s2);
    gemm_kernel<<<dim3(64 * C2, HDIM / NT), GT, SMEM_G, s2>>>(C0 + C1);
    cudaEventRecord(ev2, s2);

    scan_kernel<<<BTOT / BM2, 256>>>(W2, out, 0, C0);
    cudaStreamWaitEvent(0, ev1, 0);
    scan_kernel<<<BTOT / BM2, 256>>>(W2, out, C0, C1);
    cudaStreamWaitEvent(0, ev2, 0);
    scan_kernel<<<BTOT / BM2, 256>>>(W2, out, C0 + C1, C2);
}